// round 5
// baseline (speedup 1.0000x reference)
#include <cuda_runtime.h>

#define N_CODES 4096
#define N_EDGES 8192
#define EMB     128
#define KDIM    512
#define NNZ     65536
#define NTOT    33554432
#define KSEL    6553
#define TIE_CAP 8192

__device__ float    g_eX[N_EDGES * EMB];
__device__ int      g_icnt[N_EDGES];
__device__ float    g_A[N_CODES * KDIM];
__device__ float    g_B[N_EDGES * KDIM];
__device__ int      g_hist1[8 * 65536];
__device__ int      g_hist2[65536];
__device__ unsigned g_tiebuf[TIE_CAP];
__device__ int      g_tie_n;
__device__ int      g_b1, g_above1, g_take;
__device__ unsigned g_thr;

__device__ __forceinline__ unsigned mkey(float f) {
    unsigned u = __float_as_uint(f);
    return (u & 0x80000000u) ? ~u : (u | 0x80000000u);
}

// ---------------- zero scratch ----------------
__global__ void zero_k() {
    int i = blockIdx.x * blockDim.x + threadIdx.x, st = gridDim.x * blockDim.x;
    for (int j = i; j < 8 * 65536; j += st) g_hist1[j] = 0;
    for (int j = i; j < 65536; j += st) g_hist2[j] = 0;
    for (int j = i; j < N_EDGES * EMB; j += st) g_eX[j] = 0.f;
    for (int j = i; j < N_EDGES; j += st) g_icnt[j] = 0;
    if (i == 0) g_tie_n = 0;
}

// ---------------- edge counts + sums ----------------
__global__ void count_k(const int* __restrict__ E) {
    int i = blockIdx.x * blockDim.x + threadIdx.x;
    if (i < NNZ) atomicAdd(&g_icnt[E[i]], 1);
}
__global__ void edgesum_k(const float* __restrict__ X, const int* __restrict__ V,
                          const int* __restrict__ E) {
    int i = blockIdx.x * blockDim.x + threadIdx.x;
    int nz = i >> 5, lane = i & 31;
    if (nz >= NNZ) return;
    float4 x = ((const float4*)(X + V[nz] * EMB))[lane];
    float* d = g_eX + E[nz] * EMB + lane * 4;
    atomicAdd(d + 0, x.x); atomicAdd(d + 1, x.y);
    atomicAdd(d + 2, x.z); atomicAdd(d + 3, x.w);
}

// ---------------- build normalized operands ----------------
__global__ void build_k(const float* __restrict__ X, const float* __restrict__ W) {
    int gw = (blockIdx.x * blockDim.x + threadIdx.x) >> 5, lane = threadIdx.x & 31;
    if (gw >= (N_CODES + N_EDGES) * 4) return;
    int h = gw & 3, r = gw >> 2;
    float4 wv = ((const float4*)(W + h * EMB))[lane];
    float4 t;
    if (r < N_CODES) {
        float4 x = ((const float4*)(X + r * EMB))[lane];
        t.x = x.x * wv.x; t.y = x.y * wv.y; t.z = x.z * wv.z; t.w = x.w * wv.w;
    } else {
        int m = r - N_CODES;
        float inv = 1.0f / fmaxf((float)g_icnt[m], 1.0f);
        float4 s = ((const float4*)(g_eX + m * EMB))[lane];
        t.x = s.x * inv * wv.x; t.y = s.y * inv * wv.y;
        t.z = s.z * inv * wv.z; t.w = s.w * inv * wv.w;
    }
    float ss = t.x * t.x + t.y * t.y + t.z * t.z + t.w * t.w;
#pragma unroll
    for (int o = 16; o; o >>= 1) ss += __shfl_xor_sync(0xffffffffu, ss, o);
    float dn = 1.0f / fmaxf(sqrtf(ss), 1e-6f);
    float4 ov = make_float4(t.x * dn, t.y * dn, t.z * dn, t.w * dn);
    float* dst = (r < N_CODES) ? (g_A + r * KDIM + h * EMB)
                               : (g_B + (r - N_CODES) * KDIM + h * EMB);
    ((float4*)dst)[lane] = ov;
}

// ---------------- fp32 SGEMM: S = 0.25 * A * B^T ----------------
__global__ void __launch_bounds__(256, 2) gemm_k(float* __restrict__ C) {
    __shared__ float As[2][16][128], Bs[2][16][128];
    const int tid = threadIdx.x, bx = blockIdx.x, by = blockIdx.y;
    const float* Ag = g_A + (by << 7) * KDIM;
    const float* Bg = g_B + (bx << 7) * KDIM;
    const int r = tid >> 2, kq = (tid & 3) << 2;
    float4 pa0, pa1, pb0, pb1;
    pa0 = *(const float4*)(Ag + r * KDIM + kq);
    pa1 = *(const float4*)(Ag + (r + 64) * KDIM + kq);
    pb0 = *(const float4*)(Bg + r * KDIM + kq);
    pb1 = *(const float4*)(Bg + (r + 64) * KDIM + kq);
#define STORE_SMEM(buf) do {                                         \
    As[buf][kq+0][r]    = pa0.x; As[buf][kq+1][r]    = pa0.y;        \
    As[buf][kq+2][r]    = pa0.z; As[buf][kq+3][r]    = pa0.w;        \
    As[buf][kq+0][r+64] = pa1.x; As[buf][kq+1][r+64] = pa1.y;        \
    As[buf][kq+2][r+64] = pa1.z; As[buf][kq+3][r+64] = pa1.w;        \
    Bs[buf][kq+0][r]    = pb0.x; Bs[buf][kq+1][r]    = pb0.y;        \
    Bs[buf][kq+2][r]    = pb0.z; Bs[buf][kq+3][r]    = pb0.w;        \
    Bs[buf][kq+0][r+64] = pb1.x; Bs[buf][kq+1][r+64] = pb1.y;        \
    Bs[buf][kq+2][r+64] = pb1.z; Bs[buf][kq+3][r+64] = pb1.w;        \
} while (0)
    STORE_SMEM(0);
    __syncthreads();
    const int rn = (tid >> 4) << 3, cm = (tid & 15) << 3;
    float acc[64];
#pragma unroll
    for (int i = 0; i < 64; i++) acc[i] = 0.f;
    int cur = 0;
    for (int kt = 0; kt < 32; kt++) {
        if (kt < 31) {
            int k0 = (kt + 1) << 4;
            pa0 = *(const float4*)(Ag + r * KDIM + k0 + kq);
            pa1 = *(const float4*)(Ag + (r + 64) * KDIM + k0 + kq);
            pb0 = *(const float4*)(Bg + r * KDIM + k0 + kq);
            pb1 = *(const float4*)(Bg + (r + 64) * KDIM + k0 + kq);
        }
#pragma unroll
        for (int kk = 0; kk < 16; kk++) {
            float a[8], b[8];
            *(float4*)(a)     = *(const float4*)&As[cur][kk][rn];
            *(float4*)(a + 4) = *(const float4*)&As[cur][kk][rn + 4];
            *(float4*)(b)     = *(const float4*)&Bs[cur][kk][cm];
            *(float4*)(b + 4) = *(const float4*)&Bs[cur][kk][cm + 4];
#pragma unroll
            for (int i = 0; i < 8; i++)
#pragma unroll
                for (int j = 0; j < 8; j++)
                    acc[i * 8 + j] = fmaf(a[i], b[j], acc[i * 8 + j]);
        }
        if (kt < 31) {
            int nb = cur ^ 1;
            STORE_SMEM(nb);
            __syncthreads();
            cur = nb;
        }
    }
#undef STORE_SMEM
#pragma unroll
    for (int i = 0; i < 8; i++) {
        float* cp = C + (size_t)((by << 7) + rn + i) * N_EDGES + (bx << 7) + cm;
        *(float4*)cp = make_float4(acc[i*8+0]*0.25f, acc[i*8+1]*0.25f,
                                   acc[i*8+2]*0.25f, acc[i*8+3]*0.25f);
        *(float4*)(cp+4) = make_float4(acc[i*8+4]*0.25f, acc[i*8+5]*0.25f,
                                       acc[i*8+6]*0.25f, acc[i*8+7]*0.25f);
    }
}

// ---------------- mask existing incidences ----------------
__global__ void mask_k(const int* __restrict__ V, const int* __restrict__ E,
                       float* __restrict__ S) {
    int i = blockIdx.x * blockDim.x + threadIdx.x;
    if (i < NNZ) S[(size_t)V[i] * N_EDGES + E[i]] = -1e9f;
}

// ---------------- radix-select threshold ----------------
__global__ void hist1_k(const float4* __restrict__ S4) {
    int i = blockIdx.x * blockDim.x + threadIdx.x, st = gridDim.x * blockDim.x;
    int* h = g_hist1 + ((blockIdx.x & 7) << 16);
    for (; i < NTOT / 4; i += st) {
        float4 v = S4[i];
        atomicAdd(&h[mkey(v.x) >> 16], 1);
        atomicAdd(&h[mkey(v.y) >> 16], 1);
        atomicAdd(&h[mkey(v.z) >> 16], 1);
        atomicAdd(&h[mkey(v.w) >> 16], 1);
    }
}
__global__ void scan1_k() {
    __shared__ int tot[1024];
    int t = threadIdx.x, base = t * 64, s = 0;
    for (int j = 0; j < 64; j++) {
        int v = 0;
#pragma unroll
        for (int p = 0; p < 8; p++) v += g_hist1[(p << 16) + base + j];
        g_hist1[base + j] = v; s += v;
    }
    tot[t] = s; __syncthreads();
    int above = 0;
    for (int u = t + 1; u < 1024; u++) above += tot[u];
    for (int j = 63; j >= 0; j--) {
        int v = g_hist1[base + j];
        if (above < KSEL && above + v >= KSEL) { g_b1 = base + j; g_above1 = above; }
        above += v;
    }
}
__global__ void hist2_k(const float4* __restrict__ S4) {
    unsigned b1 = (unsigned)g_b1;
    int i = blockIdx.x * blockDim.x + threadIdx.x, st = gridDim.x * blockDim.x;
    for (; i < NTOT / 4; i += st) {
        float4 v = S4[i];
        unsigned k0 = mkey(v.x), k1 = mkey(v.y), k2 = mkey(v.z), k3 = mkey(v.w);
        if ((k0 >> 16) == b1) atomicAdd(&g_hist2[k0 & 0xFFFFu], 1);
        if ((k1 >> 16) == b1) atomicAdd(&g_hist2[k1 & 0xFFFFu], 1);
        if ((k2 >> 16) == b1) atomicAdd(&g_hist2[k2 & 0xFFFFu], 1);
        if ((k3 >> 16) == b1) atomicAdd(&g_hist2[k3 & 0xFFFFu], 1);
    }
}
__global__ void scan2_k() {
    __shared__ int tot[1024];
    int t = threadIdx.x, base = t * 64, s = 0;
    for (int j = 0; j < 64; j++) s += g_hist2[base + j];
    tot[t] = s; __syncthreads();
    int above = g_above1;
    for (int u = t + 1; u < 1024; u++) above += tot[u];
    for (int j = 63; j >= 0; j--) {
        int v = g_hist2[base + j];
        if (above < KSEL && above + v >= KSEL) {
            g_thr = ((unsigned)g_b1 << 16) | (unsigned)(base + j);
            g_take = KSEL - above;
        }
        above += v;
    }
}

// select: S[i] <- 1.0 if strictly above threshold, 0 otherwise; collect ties
__global__ void select_k(float* __restrict__ S) {
    unsigned thr = g_thr;
    int i = blockIdx.x * blockDim.x + threadIdx.x, st = gridDim.x * blockDim.x;
    for (; i < NTOT; i += st) {
        unsigned k = mkey(S[i]);
        float o = 0.f;
        if (k > thr) o = 1.f;
        else if (k == thr) {
            int p = atomicAdd(&g_tie_n, 1);
            if (p < TIE_CAP) g_tiebuf[p] = (unsigned)i;
        }
        S[i] = o;
    }
}
// pick the g_take lowest-index ties (matches lax.top_k tie order)
__global__ void tie_k(float* __restrict__ S) {
    if (threadIdx.x || blockIdx.x) return;
    int n = g_tie_n; if (n > TIE_CAP) n = TIE_CAP;
    int take = g_take; if (take > n) take = n;
    for (int r = 0; r < take; r++) {
        int bi = -1; unsigned bv = 0xFFFFFFFFu;
        for (int j = 0; j < n; j++)
            if (g_tiebuf[j] < bv) { bv = g_tiebuf[j]; bi = j; }
        S[bv] = 1.f;
        g_tiebuf[bi] = 0xFFFFFFFFu;
    }
}

// ---------------- threefry mask + final output ----------------
__device__ __forceinline__ unsigned rotl32(unsigned x, int r) {
    return __funnelshift_l(x, x, r);
}
__device__ __forceinline__ unsigned tf_bits(unsigned c0, unsigned c1) {
    const unsigned k0 = 0u, k1 = 42u, k2 = 0u ^ 42u ^ 0x1BD11BDAu;
    unsigned x0 = c0 + k0, x1 = c1 + k1;
#define TR(a) x0 += x1; x1 = rotl32(x1, a); x1 ^= x0;
    TR(13) TR(15) TR(26) TR(6)   x0 += k1; x1 += k2 + 1u;
    TR(17) TR(29) TR(16) TR(24)  x0 += k2; x1 += k0 + 2u;
    TR(13) TR(15) TR(26) TR(6)   x0 += k0; x1 += k1 + 3u;
    TR(17) TR(29) TR(16) TR(24)  x0 += k1; x1 += k2 + 4u;
    TR(13) TR(15) TR(26) TR(6)   x0 += k2; x1 += k0 + 5u;
#undef TR
    return x0 ^ x1;   // partitionable mode: out0 ^ out1, counter = (0, j)
}
__global__ void final_k(const float* __restrict__ H, const float* __restrict__ P,
                        float* __restrict__ S) {
    int i = blockIdx.x * blockDim.x + threadIdx.x;
    if (i >= NTOT) return;
    unsigned bits = tf_bits(0u, (unsigned)i);
    float u01 = __uint_as_float((bits >> 9) | 0x3f800000u) - 1.0f;
    const float MINV = 1e-6f, MAXV = (float)(1.0 - 1e-6);
    float u = fmaxf(MINV, u01 * (MAXV - MINV) + MINV);
    float p = P[i];
    float logits = (logf(p) - log1pf(-p) + logf(u) - log1pf(-u)) * 2.0f; // /TEMP
    float mask = 1.0f / (1.0f + expf(-logits));
    S[i] = (H[i] + S[i]) * mask;
}

// ---------------- launch ----------------
extern "C" void kernel_launch(void* const* d_in, const int* in_sizes, int n_in,
                              void* d_out, int out_size) {
    const float* X = (const float*)d_in[0];
    const float* H = (const float*)d_in[1];
    const int*   V = (const int*)d_in[2];
    const int*   E = (const int*)d_in[3];
    const float* P = (const float*)d_in[4];
    const float* W = (const float*)d_in[5];
    float* S = (float*)d_out;

    zero_k<<<2048, 256>>>();
    count_k<<<NNZ / 256, 256>>>(E);
    edgesum_k<<<NNZ * 32 / 256, 256>>>(X, V, E);
    build_k<<<(N_CODES + N_EDGES) * 4 * 32 / 256, 256>>>(X, W);
    dim3 gg(N_EDGES / 128, N_CODES / 128);
    gemm_k<<<gg, 256>>>(S);
    mask_k<<<NNZ / 256, 256>>>(V, E, S);
    hist1_k<<<1024, 256>>>((const float4*)S);
    scan1_k<<<1, 1024>>>();
    hist2_k<<<1024, 256>>>((const float4*)S);
    scan2_k<<<1, 1024>>>();
    select_k<<<2048, 256>>>(S);
    tie_k<<<1, 32>>>(S);
    final_k<<<(NTOT + 255) / 256, 256>>>(H, P, S);
}

// round 6
// speedup vs baseline: 1.2870x; 1.2870x over previous
#include <cuda_runtime.h>

#define N_CODES 4096
#define N_EDGES 8192
#define EMB     128
#define KDIM    512
#define NNZ     65536
#define NTOT    33554432
#define KSEL    6553
#define BAND_CAP 16384
#define SEL_CAP  8192

__device__ float    g_eX[N_EDGES * EMB];
__device__ int      g_icnt[N_EDGES];
__device__ float    g_A[N_CODES * KDIM];
__device__ float    g_B[N_EDGES * KDIM];
__device__ int      g_hist1[8 * 65536];
__device__ unsigned g_sel[SEL_CAP];
__device__ unsigned g_band[BAND_CAP];
__device__ unsigned long long g_bkey[BAND_CAP];
__device__ int      g_sel_n, g_band_n, g_b1;
__device__ float    g_tlo, g_thi;

__device__ __forceinline__ unsigned mkey(float f) {
    unsigned u = __float_as_uint(f);
    return (u & 0x80000000u) ? ~u : (u | 0x80000000u);
}
__device__ __forceinline__ float key2f(unsigned k) {
    unsigned u = (k & 0x80000000u) ? (k ^ 0x80000000u) : ~k;
    return __uint_as_float(u);
}

// ---------------- zero scratch ----------------
__global__ void zero_k() {
    int i = blockIdx.x * blockDim.x + threadIdx.x, st = gridDim.x * blockDim.x;
    for (int j = i; j < 8 * 65536; j += st) g_hist1[j] = 0;
    for (int j = i; j < N_EDGES * EMB; j += st) g_eX[j] = 0.f;
    for (int j = i; j < N_EDGES; j += st) g_icnt[j] = 0;
    if (i == 0) { g_sel_n = 0; g_band_n = 0; }
}

// ---------------- edge counts + sums ----------------
__global__ void count_k(const int* __restrict__ E) {
    int i = blockIdx.x * blockDim.x + threadIdx.x;
    if (i < NNZ) atomicAdd(&g_icnt[E[i]], 1);
}
__global__ void edgesum_k(const float* __restrict__ X, const int* __restrict__ V,
                          const int* __restrict__ E) {
    int i = blockIdx.x * blockDim.x + threadIdx.x;
    int nz = i >> 5, lane = i & 31;
    if (nz >= NNZ) return;
    float4 x = ((const float4*)(X + V[nz] * EMB))[lane];
    float* d = g_eX + E[nz] * EMB + lane * 4;
    atomicAdd(d + 0, x.x); atomicAdd(d + 1, x.y);
    atomicAdd(d + 2, x.z); atomicAdd(d + 3, x.w);
}

// ---------------- build normalized operands ----------------
__global__ void build_k(const float* __restrict__ X, const float* __restrict__ W) {
    int gw = (blockIdx.x * blockDim.x + threadIdx.x) >> 5, lane = threadIdx.x & 31;
    if (gw >= (N_CODES + N_EDGES) * 4) return;
    int h = gw & 3, r = gw >> 2;
    float4 wv = ((const float4*)(W + h * EMB))[lane];
    float4 t;
    if (r < N_CODES) {
        float4 x = ((const float4*)(X + r * EMB))[lane];
        t.x = x.x * wv.x; t.y = x.y * wv.y; t.z = x.z * wv.z; t.w = x.w * wv.w;
    } else {
        int m = r - N_CODES;
        float inv = 1.0f / fmaxf((float)g_icnt[m], 1.0f);
        float4 s = ((const float4*)(g_eX + m * EMB))[lane];
        t.x = s.x * inv * wv.x; t.y = s.y * inv * wv.y;
        t.z = s.z * inv * wv.z; t.w = s.w * inv * wv.w;
    }
    float ss = t.x * t.x + t.y * t.y + t.z * t.z + t.w * t.w;
#pragma unroll
    for (int o = 16; o; o >>= 1) ss += __shfl_xor_sync(0xffffffffu, ss, o);
    float dn = 1.0f / fmaxf(sqrtf(ss), 1e-6f);
    float4 ov = make_float4(t.x * dn, t.y * dn, t.z * dn, t.w * dn);
    float* dst = (r < N_CODES) ? (g_A + r * KDIM + h * EMB)
                               : (g_B + (r - N_CODES) * KDIM + h * EMB);
    ((float4*)dst)[lane] = ov;
}

// ---------------- 3xTF32 tensor-core GEMM: S = 0.25 * A * B^T ----------------
__device__ __forceinline__ unsigned f2tf(float x) {
    unsigned r; asm("cvt.rna.tf32.f32 %0, %1;" : "=r"(r) : "f"(x)); return r;
}
__device__ __forceinline__ void mma8(float* d, const unsigned* a, const unsigned* b) {
    asm volatile("mma.sync.aligned.m16n8k8.row.col.f32.tf32.tf32.f32 "
        "{%0,%1,%2,%3}, {%4,%5,%6,%7}, {%8,%9}, {%0,%1,%2,%3};\n"
        : "+f"(d[0]), "+f"(d[1]), "+f"(d[2]), "+f"(d[3])
        : "r"(a[0]), "r"(a[1]), "r"(a[2]), "r"(a[3]), "r"(b[0]), "r"(b[1]));
}
#define SW(r,k) (((r) << 5) + ((k) ^ (((r) & 7) << 2)))

__global__ void __launch_bounds__(256, 1) gemm_k(float* __restrict__ C) {
    __shared__ unsigned Ah[128 * 32], Al[128 * 32];
    __shared__ float    Bf[128 * 32];
    const int tid = threadIdx.x, bx = blockIdx.x, by = blockIdx.y;
    const float* Ag = g_A + (size_t)(by << 7) * KDIM;
    const float* Bg = g_B + (size_t)(bx << 7) * KDIM;
    const int wid = tid >> 5, lane = tid & 31;
    const int wm = wid & 1, wn = wid >> 1;
    const int ldrow = tid >> 3, ldk = (tid & 7) << 2;
    float4 pa[4], pb[4];
#define GLOAD(cc) {                                                              \
    int kb = (cc) << 5;                                                          \
    _Pragma("unroll")                                                            \
    for (int i = 0; i < 4; i++) {                                                \
        pa[i] = *(const float4*)(Ag + (size_t)(ldrow + 32*i)*KDIM + kb + ldk);   \
        pb[i] = *(const float4*)(Bg + (size_t)(ldrow + 32*i)*KDIM + kb + ldk);   \
    } }
    float d[4][4][4];
#pragma unroll
    for (int i = 0; i < 4; i++)
#pragma unroll
        for (int j = 0; j < 4; j++)
#pragma unroll
            for (int q = 0; q < 4; q++) d[i][j][q] = 0.f;
    GLOAD(0);
    for (int c = 0; c < 16; c++) {
#pragma unroll
        for (int i = 0; i < 4; i++) {
            int r = ldrow + 32 * i;
            int ph = SW(r, ldk);
            float4 x = pa[i];
            unsigned h0 = f2tf(x.x), h1 = f2tf(x.y), h2 = f2tf(x.z), h3 = f2tf(x.w);
            *(uint4*)&Ah[ph] = make_uint4(h0, h1, h2, h3);
            *(uint4*)&Al[ph] = make_uint4(f2tf(x.x - __uint_as_float(h0)),
                                          f2tf(x.y - __uint_as_float(h1)),
                                          f2tf(x.z - __uint_as_float(h2)),
                                          f2tf(x.w - __uint_as_float(h3)));
            *(float4*)&Bf[ph] = pb[i];
        }
        __syncthreads();
        if (c + 1 < 16) GLOAD(c + 1);
#pragma unroll
        for (int ks = 0; ks < 4; ks++) {
            int k0 = (ks << 3) + (lane & 3);
            unsigned ah[4][4], al[4][4], bh[4][2], bl[4][2];
#pragma unroll
            for (int mt = 0; mt < 4; mt++) {
                int r = (wm << 6) + (mt << 4) + (lane >> 2);
                ah[mt][0] = Ah[SW(r, k0)];     ah[mt][1] = Ah[SW(r + 8, k0)];
                ah[mt][2] = Ah[SW(r, k0 + 4)]; ah[mt][3] = Ah[SW(r + 8, k0 + 4)];
                al[mt][0] = Al[SW(r, k0)];     al[mt][1] = Al[SW(r + 8, k0)];
                al[mt][2] = Al[SW(r, k0 + 4)]; al[mt][3] = Al[SW(r + 8, k0 + 4)];
            }
#pragma unroll
            for (int nt = 0; nt < 4; nt++) {
                int n = (wn << 5) + (nt << 3) + (lane >> 2);
                float x0 = Bf[SW(n, k0)], x1 = Bf[SW(n, k0 + 4)];
                bh[nt][0] = f2tf(x0); bl[nt][0] = f2tf(x0 - __uint_as_float(bh[nt][0]));
                bh[nt][1] = f2tf(x1); bl[nt][1] = f2tf(x1 - __uint_as_float(bh[nt][1]));
            }
#pragma unroll
            for (int mt = 0; mt < 4; mt++)
#pragma unroll
                for (int nt = 0; nt < 4; nt++) {
                    mma8(d[mt][nt], al[mt], bh[nt]);
                    mma8(d[mt][nt], ah[mt], bl[nt]);
                    mma8(d[mt][nt], ah[mt], bh[nt]);
                }
        }
        __syncthreads();
    }
#pragma unroll
    for (int mt = 0; mt < 4; mt++) {
        int rg = (by << 7) + (wm << 6) + (mt << 4) + (lane >> 2);
#pragma unroll
        for (int nt = 0; nt < 4; nt++) {
            int cg = (bx << 7) + (wn << 5) + (nt << 3) + ((lane & 3) << 1);
            *(float2*)(C + (size_t)rg * N_EDGES + cg) =
                make_float2(d[mt][nt][0] * 0.25f, d[mt][nt][1] * 0.25f);
            *(float2*)(C + (size_t)(rg + 8) * N_EDGES + cg) =
                make_float2(d[mt][nt][2] * 0.25f, d[mt][nt][3] * 0.25f);
        }
    }
}
#undef GLOAD

// ---------------- mask existing incidences ----------------
__global__ void mask_k(const int* __restrict__ V, const int* __restrict__ E,
                       float* __restrict__ S) {
    int i = blockIdx.x * blockDim.x + threadIdx.x;
    if (i < NNZ) S[(size_t)V[i] * N_EDGES + E[i]] = -1e9f;
}

// ---------------- 16-bit radix histogram -> threshold band ----------------
__global__ void hist1_k(const float4* __restrict__ S4) {
    int i = blockIdx.x * blockDim.x + threadIdx.x, st = gridDim.x * blockDim.x;
    int* h = g_hist1 + ((blockIdx.x & 7) << 16);
    for (; i < NTOT / 4; i += st) {
        float4 v = S4[i];
        atomicAdd(&h[mkey(v.x) >> 16], 1);
        atomicAdd(&h[mkey(v.y) >> 16], 1);
        atomicAdd(&h[mkey(v.z) >> 16], 1);
        atomicAdd(&h[mkey(v.w) >> 16], 1);
    }
}
__global__ void scan1_k() {
    __shared__ int tot[1024];
    int t = threadIdx.x, base = t * 64, s = 0;
    for (int j = 0; j < 64; j++) {
        int v = 0;
#pragma unroll
        for (int p = 0; p < 8; p++) v += g_hist1[(p << 16) + base + j];
        g_hist1[base + j] = v; s += v;
    }
    tot[t] = s; __syncthreads();
    int above = 0;
    for (int u = t + 1; u < 1024; u++) above += tot[u];
    for (int j = 63; j >= 0; j--) {
        int v = g_hist1[base + j];
        if (above < KSEL && above + v >= KSEL) {
            int b1 = base + j;
            g_b1 = b1;
            unsigned klo = (unsigned)b1 << 16;
            unsigned khi = klo + 0x10000u;
            g_tlo = key2f(klo) - 3e-5f;
            g_thi = key2f(khi) + 3e-5f;
        }
        above += v;
    }
}

// certain-selected above band; ambiguous entries into band buffer
__global__ void collect_k(const float* __restrict__ S) {
    float tlo = g_tlo, thi = g_thi;
    int i = blockIdx.x * blockDim.x + threadIdx.x, st = gridDim.x * blockDim.x;
    for (; i < NTOT; i += st) {
        float v = S[i];
        if (v > tlo) {
            if (v > thi) {
                int p = atomicAdd(&g_sel_n, 1);
                if (p < SEL_CAP) g_sel[p] = (unsigned)i;
            } else {
                int p = atomicAdd(&g_band_n, 1);
                if (p < BAND_CAP) g_band[p] = (unsigned)i;
            }
        }
    }
}

// fp64 recompute of band entries (one warp per entry)
__global__ void exactval_k() {
    int nb = g_band_n; if (nb > BAND_CAP) nb = BAND_CAP;
    int j = blockIdx.x * 8 + (threadIdx.x >> 5);
    if (j >= nb) return;
    int lane = threadIdx.x & 31;
    unsigned idx = g_band[j];
    const float* a = g_A + (size_t)(idx >> 13) * KDIM;
    const float* b = g_B + (size_t)(idx & 8191) * KDIM;
    double s = 0.0;
    for (int t = lane; t < KDIM; t += 32) s += (double)a[t] * (double)b[t];
#pragma unroll
    for (int o = 16; o; o >>= 1) s += __shfl_down_sync(0xffffffffu, s, o);
    if (lane == 0) {
        unsigned long long u = (unsigned long long)__double_as_longlong(s * 0.25);
        g_bkey[j] = (u & 0x8000000000000000ull) ? ~u : (u | 0x8000000000000000ull);
    }
}

// radix-select the remaining slots from the band (ties -> lowest index)
__global__ void bandsel_k() {
    __shared__ int red[8];
    __shared__ int s_tot, s_n;
    int nb = g_band_n; if (nb > BAND_CAP) nb = BAND_CAP;
    int nsel = g_sel_n; if (nsel > SEL_CAP) nsel = SEL_CAP;
    int t = KSEL - nsel;
    int tid = threadIdx.x, lane = tid & 31, wid = tid >> 5;
    if (t <= 0) { if (tid == 0) g_sel_n = nsel; return; }
    if (t >= nb) {
        for (int j = tid; j < nb; j += 256) g_sel[nsel + j] = g_band[j];
        if (tid == 0) g_sel_n = nsel + nb;
        return;
    }
    unsigned long long cur = 0;
    for (int b = 63; b >= 0; b--) {
        unsigned long long test = cur | (1ull << b);
        int c = 0;
        for (int j = tid; j < nb; j += 256) if (g_bkey[j] >= test) c++;
#pragma unroll
        for (int o = 16; o; o >>= 1) c += __shfl_down_sync(0xffffffffu, c, o);
        if (lane == 0) red[wid] = c;
        __syncthreads();
        if (tid == 0) { int s = 0; for (int w = 0; w < 8; w++) s += red[w]; s_tot = s; }
        __syncthreads();
        if (s_tot >= t) cur = test;
        __syncthreads();
    }
    if (tid == 0) s_n = nsel;
    __syncthreads();
    for (int j = tid; j < nb; j += 256)
        if (g_bkey[j] > cur) { int p = atomicAdd(&s_n, 1); g_sel[p] = g_band[j]; }
    __syncthreads();
    if (tid == 0) {
        int need = KSEL - s_n;
        while (need > 0) {
            unsigned best = 0xFFFFFFFFu; int bj = -1;
            for (int j = 0; j < nb; j++)
                if (g_bkey[j] == cur && g_band[j] < best) { best = g_band[j]; bj = j; }
            if (bj < 0) break;
            g_sel[s_n++] = best; g_bkey[bj] = 0; need--;
        }
        g_sel_n = s_n;
    }
}

// ---------------- threefry mask (bit-exact vs R5-validated path) ----------------
__device__ __forceinline__ unsigned rotl32(unsigned x, int r) {
    return __funnelshift_l(x, x, r);
}
__device__ __forceinline__ unsigned tf_bits(unsigned c0, unsigned c1) {
    const unsigned k0 = 0u, k1 = 42u, k2 = 0u ^ 42u ^ 0x1BD11BDAu;
    unsigned x0 = c0 + k0, x1 = c1 + k1;
#define TR(a) x0 += x1; x1 = rotl32(x1, a); x1 ^= x0;
    TR(13) TR(15) TR(26) TR(6)   x0 += k1; x1 += k2 + 1u;
    TR(17) TR(29) TR(16) TR(24)  x0 += k2; x1 += k0 + 2u;
    TR(13) TR(15) TR(26) TR(6)   x0 += k0; x1 += k1 + 3u;
    TR(17) TR(29) TR(16) TR(24)  x0 += k1; x1 += k2 + 4u;
    TR(13) TR(15) TR(26) TR(6)   x0 += k2; x1 += k0 + 5u;
#undef TR
    return x0 ^ x1;
}
__device__ __forceinline__ float maskval(unsigned idx, float p) {
    unsigned bits = tf_bits(0u, idx);
    float u01 = __uint_as_float((bits >> 9) | 0x3f800000u) - 1.0f;
    const float MINV = 1e-6f, MAXV = (float)(1.0 - 1e-6);
    float u = fmaxf(MINV, u01 * (MAXV - MINV) + MINV);
    float lg = (logf(p) - log1pf(-p) + logf(u) - log1pf(-u)) * 2.0f;
    return 1.0f / (1.0f + expf(-lg));
}

__global__ void zeroout_k(float4* __restrict__ o) {
    int i = blockIdx.x * blockDim.x + threadIdx.x, st = gridDim.x * blockDim.x;
    float4 z = make_float4(0.f, 0.f, 0.f, 0.f);
    for (; i < NTOT / 4; i += st) o[i] = z;
}
__global__ void scat_old_k(const int* __restrict__ V, const int* __restrict__ E,
                           const float* __restrict__ P, float* __restrict__ out) {
    int i = blockIdx.x * blockDim.x + threadIdx.x;
    if (i >= NNZ) return;
    unsigned idx = (unsigned)V[i] * N_EDGES + (unsigned)E[i];
    out[idx] = maskval(idx, P[idx]);
}
__global__ void scat_new_k(const float* __restrict__ P, float* __restrict__ out) {
    int i = blockIdx.x * blockDim.x + threadIdx.x;
    if (i >= g_sel_n) return;
    unsigned idx = g_sel[i];
    out[idx] = maskval(idx, P[idx]);
}

// ---------------- launch ----------------
extern "C" void kernel_launch(void* const* d_in, const int* in_sizes, int n_in,
                              void* d_out, int out_size) {
    const float* X = (const float*)d_in[0];
    const int*   V = (const int*)d_in[2];
    const int*   E = (const int*)d_in[3];
    const float* P = (const float*)d_in[4];
    const float* W = (const float*)d_in[5];
    float* S = (float*)d_out;

    zero_k<<<2048, 256>>>();
    count_k<<<NNZ / 256, 256>>>(E);
    edgesum_k<<<NNZ * 32 / 256, 256>>>(X, V, E);
    build_k<<<(N_CODES + N_EDGES) * 4 * 32 / 256, 256>>>(X, W);
    gemm_k<<<dim3(N_EDGES / 128, N_CODES / 128), 256>>>(S);
    mask_k<<<NNZ / 256, 256>>>(V, E, S);
    hist1_k<<<1024, 256>>>((const float4*)S);
    scan1_k<<<1, 1024>>>();
    collect_k<<<2048, 256>>>(S);
    exactval_k<<<BAND_CAP / 8, 256>>>();
    bandsel_k<<<1, 256>>>();
    zeroout_k<<<2048, 256>>>((float4*)S);
    scat_old_k<<<NNZ / 256, 256>>>(V, E, P, S);
    scat_new_k<<<32, 256>>>(P, S);
}